// round 2
// baseline (speedup 1.0000x reference)
#include <cuda_runtime.h>

// DeformConv3d, dimension='HW': t-offset == 0 -> pure 2D bilinear at integer t.
//   x:      [2, 16, 8, 64, 64]  fp32
//   temp:   [2, 54, 8, 64, 64]  fp32
//   weight: [16, 16, 3, 3, 3]   fp32
//   bias:   [16]                fp32
//   out:    [2, 16, 8, 64, 64]  fp32
//
// R2: channels-last transpose of x (corner loads -> 4x LDG.128) + 3-way kt
// split per output point (3x warp parallelism) + f32x2 packed GEMM.

#define NB  2
#define NC  16
#define NT  8
#define NH  64
#define NW  64
#define NCO 16
#define NK  27
#define HW  (NH * NW)     // 4096
#define THW (NT * HW)     // 32768

// packed dual-fp32 FMA: d = a*b + d
#define FMA2(d, a, b) \
    asm("fma.rn.f32x2 %0, %1, %2, %0;" : "+l"(d) : "l"(a), "l"(b))
#define PACK2(d, lo, hi) \
    asm("mov.b64 %0, {%1, %2};" : "=l"(d) : "f"(lo), "f"(hi))
#define UNPACK2(lo, hi, s) \
    asm("mov.b64 {%0, %1}, %2;" : "=f"(lo), "=f"(hi) : "l"(s))

// channels-last copy of x (scratch; no allocation allowed in kernel_launch)
__device__ float g_xt[NB * THW * NC];

// ---------------------------------------------------------------------------
// Transpose x[b][c][thw] -> xt[b][thw][c], tiled through smem so both sides
// are coalesced.
__global__ void transpose_x_kernel(const float* __restrict__ x)
{
    __shared__ float tile[NC][64 + 1];
    const int b   = blockIdx.y;
    const int hw0 = blockIdx.x * 64;

    // load: 256 threads, coalesced along hw
    {
        const int lx = threadIdx.x & 63;
        const int c0 = threadIdx.x >> 6;      // 0..3
#pragma unroll
        for (int c = c0; c < NC; c += 4)
            tile[c][lx] = x[(b * NC + c) * THW + hw0 + lx];
    }
    __syncthreads();
    // store: coalesced along c (16 floats per hw)
    {
        const int c  = threadIdx.x & 15;
        const int h0 = threadIdx.x >> 4;      // 0..15
#pragma unroll
        for (int hw = h0; hw < 64; hw += 16)
            g_xt[(b * THW + hw0 + hw) * NC + c] = tile[c][hw];
    }
}

// ---------------------------------------------------------------------------
// Main kernel. Block = 192 threads = 3 parts x 64 outputs (one (b,t,h) row).
// part p handles ti = t-1+p (9 taps); parts reduce through smem.
#define TPB 192

__global__ void __launch_bounds__(TPB, 4)
deform_conv3d_hw_kernel(const float* __restrict__ temp,
                        const float* __restrict__ wgt,
                        const float* __restrict__ bias,
                        float* __restrict__ out)
{
    // weights as [k][c][co]: 16 contiguous co per (k,c) -> LDS.128 broadcast
    __shared__ __align__(16) float wsm[NK * NC * NCO];          // 27648 B
    __shared__ __align__(16) unsigned long long redsm[2][64][8]; // 8192 B

    for (int i = threadIdx.x; i < NK * NC * NCO; i += TPB) {
        int co = i & 15;
        int c  = (i >> 4) & 15;
        int k  = i >> 8;
        wsm[i] = wgt[(co * NC + c) * NK + k];
    }

    const int part = threadIdx.x / 64;   // warp-coherent: warps 0,1 = part 0 ...
    const int lane = threadIdx.x & 63;   // = w
    const int row  = blockIdx.x;         // b*512 + t*64 + h
    const int w = lane;
    const int h = row & 63;
    const int t = (row >> 6) & 7;
    const int b = row >> 9;
    const int sp = t * HW + h * NW + w;

    unsigned long long acc[8];
    if (part == 0) {
#pragma unroll
        for (int j = 0; j < 8; j++)
            PACK2(acc[j], bias[2 * j], bias[2 * j + 1]);
    } else {
#pragma unroll
        for (int j = 0; j < 8; j++) acc[j] = 0ULL;
    }

    __syncthreads();   // wsm ready

    const int ti = t - 1 + part;
    if (ti >= 0 && ti < NT) {
        const float* __restrict__ plane = g_xt + (b * NT + ti) * (HW * NC);
        const float* __restrict__ tb = temp + b * (2 * NK * THW) + sp;
        const int kbase = part * 9;

#pragma unroll
        for (int kh = 0; kh < 3; kh++) {
#pragma unroll
            for (int kw = 0; kw < 3; kw++) {
                const int k = kbase + kh * 3 + kw;

                const float offh = __ldg(tb + (2 * k) * THW);
                const float offw = __ldg(tb + (2 * k + 1) * THW);

                const float ph = (float)(h - 1 + kh) + offh;
                const float pw = (float)(w - 1 + kw) + offw;

                const int h0 = __float2int_rd(ph);
                const int w0 = __float2int_rd(pw);
                const float fh = ph - (float)h0;
                const float fw = pw - (float)w0;
                const int h1 = h0 + 1;
                const int w1 = w0 + 1;

                const bool vh0 = (h0 >= 0) & (h0 < NH);
                const bool vh1 = (h1 >= 0) & (h1 < NH);
                const bool vw0 = (w0 >= 0) & (w0 < NW);
                const bool vw1 = (w1 >= 0) & (w1 < NW);

                const float gh0 = 1.0f - fh, gw0 = 1.0f - fw;
                const float c00 = (vh0 & vw0) ? gh0 * gw0 : 0.0f;
                const float c01 = (vh0 & vw1) ? gh0 * fw  : 0.0f;
                const float c10 = (vh1 & vw0) ? fh  * gw0 : 0.0f;
                const float c11 = (vh1 & vw1) ? fh  * fw  : 0.0f;

                const int h0c = min(max(h0, 0), NH - 1);
                const int h1c = min(max(h1, 0), NH - 1);
                const int w0c = min(max(w0, 0), NW - 1);
                const int w1c = min(max(w1, 0), NW - 1);

                const int i00 = h0c * NW + w0c;
                const int i01 = h0c * NW + w1c;
                const int i10 = h1c * NW + w0c;
                const int i11 = h1c * NW + w1c;

                unsigned long long cc00, cc01, cc10, cc11;
                PACK2(cc00, c00, c00);
                PACK2(cc01, c01, c01);
                PACK2(cc10, c10, c10);
                PACK2(cc11, c11, c11);

                // gather: val[j] = packed channels {2j, 2j+1}
                unsigned long long val[8];
#pragma unroll
                for (int j = 0; j < 8; j++) val[j] = 0ULL;

                {
                    const ulonglong2* p =
                        (const ulonglong2*)(plane + i00 * NC);
                    ulonglong2 a0 = p[0], a1 = p[1], a2 = p[2], a3 = p[3];
                    FMA2(val[0], cc00, a0.x); FMA2(val[1], cc00, a0.y);
                    FMA2(val[2], cc00, a1.x); FMA2(val[3], cc00, a1.y);
                    FMA2(val[4], cc00, a2.x); FMA2(val[5], cc00, a2.y);
                    FMA2(val[6], cc00, a3.x); FMA2(val[7], cc00, a3.y);
                }
                {
                    const ulonglong2* p =
                        (const ulonglong2*)(plane + i01 * NC);
                    ulonglong2 a0 = p[0], a1 = p[1], a2 = p[2], a3 = p[3];
                    FMA2(val[0], cc01, a0.x); FMA2(val[1], cc01, a0.y);
                    FMA2(val[2], cc01, a1.x); FMA2(val[3], cc01, a1.y);
                    FMA2(val[4], cc01, a2.x); FMA2(val[5], cc01, a2.y);
                    FMA2(val[6], cc01, a3.x); FMA2(val[7], cc01, a3.y);
                }
                {
                    const ulonglong2* p =
                        (const ulonglong2*)(plane + i10 * NC);
                    ulonglong2 a0 = p[0], a1 = p[1], a2 = p[2], a3 = p[3];
                    FMA2(val[0], cc10, a0.x); FMA2(val[1], cc10, a0.y);
                    FMA2(val[2], cc10, a1.x); FMA2(val[3], cc10, a1.y);
                    FMA2(val[4], cc10, a2.x); FMA2(val[5], cc10, a2.y);
                    FMA2(val[6], cc10, a3.x); FMA2(val[7], cc10, a3.y);
                }
                {
                    const ulonglong2* p =
                        (const ulonglong2*)(plane + i11 * NC);
                    ulonglong2 a0 = p[0], a1 = p[1], a2 = p[2], a3 = p[3];
                    FMA2(val[0], cc11, a0.x); FMA2(val[1], cc11, a0.y);
                    FMA2(val[2], cc11, a1.x); FMA2(val[3], cc11, a1.y);
                    FMA2(val[4], cc11, a2.x); FMA2(val[5], cc11, a2.y);
                    FMA2(val[6], cc11, a3.x); FMA2(val[7], cc11, a3.y);
                }

                // GEMM: acc[m] (co pair) += val_c * w[k][c][co]
                const ulonglong2* __restrict__ wr =
                    (const ulonglong2*)(wsm + k * (NC * NCO));
#pragma unroll
                for (int j = 0; j < 8; j++) {
                    float v0, v1;
                    UNPACK2(v0, v1, val[j]);
                    unsigned long long vv0, vv1;
                    PACK2(vv0, v0, v0);
                    PACK2(vv1, v1, v1);

                    const ulonglong2 q0 = wr[(2 * j) * 4 + 0];
                    const ulonglong2 q1 = wr[(2 * j) * 4 + 1];
                    const ulonglong2 q2 = wr[(2 * j) * 4 + 2];
                    const ulonglong2 q3 = wr[(2 * j) * 4 + 3];
                    FMA2(acc[0], vv0, q0.x); FMA2(acc[1], vv0, q0.y);
                    FMA2(acc[2], vv0, q1.x); FMA2(acc[3], vv0, q1.y);
                    FMA2(acc[4], vv0, q2.x); FMA2(acc[5], vv0, q2.y);
                    FMA2(acc[6], vv0, q3.x); FMA2(acc[7], vv0, q3.y);

                    const ulonglong2 r0 = wr[(2 * j + 1) * 4 + 0];
                    const ulonglong2 r1 = wr[(2 * j + 1) * 4 + 1];
                    const ulonglong2 r2 = wr[(2 * j + 1) * 4 + 2];
                    const ulonglong2 r3 = wr[(2 * j + 1) * 4 + 3];
                    FMA2(acc[0], vv1, r0.x); FMA2(acc[1], vv1, r0.y);
                    FMA2(acc[2], vv1, r1.x); FMA2(acc[3], vv1, r1.y);
                    FMA2(acc[4], vv1, r2.x); FMA2(acc[5], vv1, r2.y);
                    FMA2(acc[6], vv1, r3.x); FMA2(acc[7], vv1, r3.y);
                }
            }
        }
    }

    // reduce parts 1,2 into part 0 through smem
    if (part > 0) {
#pragma unroll
        for (int j = 0; j < 8; j++)
            redsm[part - 1][lane][j] = acc[j];
    }
    __syncthreads();

    if (part == 0) {
        float* ob = out + b * (NCO * THW) + sp;
#pragma unroll
        for (int j = 0; j < 8; j++) {
            float a0, a1, p0, p1, q0, q1;
            UNPACK2(a0, a1, acc[j]);
            UNPACK2(p0, p1, redsm[0][lane][j]);
            UNPACK2(q0, q1, redsm[1][lane][j]);
            ob[(2 * j) * THW]     = a0 + p0 + q0;
            ob[(2 * j + 1) * THW] = a1 + p1 + q1;
        }
    }
}

extern "C" void kernel_launch(void* const* d_in, const int* in_sizes, int n_in,
                              void* d_out, int out_size)
{
    const float* x    = (const float*)d_in[0];
    const float* temp = (const float*)d_in[1];
    const float* wgt  = (const float*)d_in[2];
    const float* bias = (const float*)d_in[3];
    float* out = (float*)d_out;

    dim3 tgrid(THW / 64, NB);
    transpose_x_kernel<<<tgrid, 256>>>(x);

    const int rows = NB * NT * NH;   // 1024 blocks of 192 threads
    deform_conv3d_hw_kernel<<<rows, TPB>>>(temp, wgt, bias, out);
}

// round 3
// speedup vs baseline: 1.0239x; 1.0239x over previous
#include <cuda_runtime.h>

// DeformConv3d, dimension='HW': t-offset == 0 -> pure 2D bilinear at integer t.
//   x:      [2, 16, 8, 64, 64]  fp32   (channels-first, kept as-is: coalesced gathers)
//   temp:   [2, 54, 8, 64, 64]  fp32
//   weight: [16, 16, 3, 3, 3]   fp32 -> __constant__ [k][c][co] (LDCU, off the L1 port)
//   bias:   [16]
//   out:    [2, 16, 8, 64, 64]  fp32
//
// R3: channels-first gathers (R1) + kt 3-way split (R2 occupancy) + weights in
// constant memory via uniform loads instead of smem LDS.

#define NB  2
#define NC  16
#define NT  8
#define NH  64
#define NW  64
#define NCO 16
#define NK  27
#define HW  (NH * NW)     // 4096
#define THW (NT * HW)     // 32768

#define FMA2(d, a, b) \
    asm("fma.rn.f32x2 %0, %1, %2, %0;" : "+l"(d) : "l"(a), "l"(b))
#define PACK2(d, lo, hi) \
    asm("mov.b64 %0, {%1, %2};" : "=l"(d) : "f"(lo), "f"(hi))
#define UNPACK2(lo, hi, s) \
    asm("mov.b64 {%0, %1}, %2;" : "=f"(lo), "=f"(hi) : "l"(s))

// weights, transposed to [k][c][co] (co contiguous -> LDCU.128)
__constant__ __align__(16) float cw[NK * NC * NCO];
__device__   __align__(16) float g_wt[NK * NC * NCO];

__global__ void transpose_w_kernel(const float* __restrict__ wgt)
{
    int i = blockIdx.x * blockDim.x + threadIdx.x;
    if (i < NK * NC * NCO) {
        int co = i & 15;
        int c  = (i >> 4) & 15;
        int k  = i >> 8;
        g_wt[i] = wgt[(co * NC + c) * NK + k];
    }
}

// ---------------------------------------------------------------------------
// Block = 192 threads = 3 kt-parts x 64 outputs (one (b,t,h) row).
#define TPB 192

__global__ void __launch_bounds__(TPB, 4)
deform_conv3d_hw_kernel(const float* __restrict__ x,
                        const float* __restrict__ temp,
                        const float* __restrict__ bias,
                        float* __restrict__ out)
{
    __shared__ __align__(16) unsigned long long redsm[2][64][8];

    const int part = threadIdx.x / 64;   // warp-coherent (warps 0,1 | 2,3 | 4,5)
    const int lane = threadIdx.x & 63;
    const int row  = blockIdx.x;         // b*512 + t*64 + h
    const int w = lane;
    const int h = row & 63;
    const int t = (row >> 6) & 7;
    const int b = row >> 9;
    const int sp = t * HW + h * NW + w;

    unsigned long long acc[8];
    if (part == 0) {
#pragma unroll
        for (int j = 0; j < 8; j++)
            PACK2(acc[j], bias[2 * j], bias[2 * j + 1]);
    } else {
#pragma unroll
        for (int j = 0; j < 8; j++) acc[j] = 0ULL;
    }

    const int ti = t - 1 + part;
    if (ti >= 0 && ti < NT) {
        const float* __restrict__ xb = x + b * (NC * THW) + ti * HW;
        const float* __restrict__ tb = temp + b * (2 * NK * THW) + sp;
        const int kbase = part * 9;

#pragma unroll
        for (int kh = 0; kh < 3; kh++) {
#pragma unroll
            for (int kw = 0; kw < 3; kw++) {
                const int k = kbase + kh * 3 + kw;

                const float offh = __ldg(tb + (2 * k) * THW);
                const float offw = __ldg(tb + (2 * k + 1) * THW);

                const float ph = (float)(h - 1 + kh) + offh;
                const float pw = (float)(w - 1 + kw) + offw;

                const int h0 = __float2int_rd(ph);
                const int w0 = __float2int_rd(pw);
                const float fh = ph - (float)h0;
                const float fw = pw - (float)w0;
                const int h1 = h0 + 1;
                const int w1 = w0 + 1;

                const bool vh0 = (h0 >= 0) & (h0 < NH);
                const bool vh1 = (h1 >= 0) & (h1 < NH);
                const bool vw0 = (w0 >= 0) & (w0 < NW);
                const bool vw1 = (w1 >= 0) & (w1 < NW);

                const float gh0 = 1.0f - fh, gw0 = 1.0f - fw;
                const float c00 = (vh0 & vw0) ? gh0 * gw0 : 0.0f;
                const float c01 = (vh0 & vw1) ? gh0 * fw  : 0.0f;
                const float c10 = (vh1 & vw0) ? fh  * gw0 : 0.0f;
                const float c11 = (vh1 & vw1) ? fh  * fw  : 0.0f;

                const int h0c = min(max(h0, 0), NH - 1);
                const int h1c = min(max(h1, 0), NH - 1);
                const int w0c = min(max(w0, 0), NW - 1);
                const int w1c = min(max(w1, 0), NW - 1);

                const int i00 = h0c * NW + w0c;
                const int i01 = h0c * NW + w1c;
                const int i10 = h1c * NW + w0c;
                const int i11 = h1c * NW + w1c;

#pragma unroll
                for (int c = 0; c < NC; c++) {
                    const float* pc = xb + c * THW;
                    float v = c11 * __ldg(pc + i11);
                    v = fmaf(c10, __ldg(pc + i10), v);
                    v = fmaf(c01, __ldg(pc + i01), v);
                    v = fmaf(c00, __ldg(pc + i00), v);

                    unsigned long long vv;
                    asm("mov.b64 %0, {%1, %1};" : "=l"(vv) : "f"(v));

                    // 16 co-weights for (k,c), contiguous in constant memory.
                    const ulonglong2* wr =
                        (const ulonglong2*)(cw + (k * NC + c) * NCO);
                    const ulonglong2 q0 = wr[0];
                    const ulonglong2 q1 = wr[1];
                    const ulonglong2 q2 = wr[2];
                    const ulonglong2 q3 = wr[3];
                    FMA2(acc[0], vv, q0.x); FMA2(acc[1], vv, q0.y);
                    FMA2(acc[2], vv, q1.x); FMA2(acc[3], vv, q1.y);
                    FMA2(acc[4], vv, q2.x); FMA2(acc[5], vv, q2.y);
                    FMA2(acc[6], vv, q3.x); FMA2(acc[7], vv, q3.y);
                }
            }
        }
    }

    if (part > 0) {
#pragma unroll
        for (int j = 0; j < 8; j++)
            redsm[part - 1][lane][j] = acc[j];
    }
    __syncthreads();

    if (part == 0) {
        float* ob = out + b * (NCO * THW) + sp;
#pragma unroll
        for (int j = 0; j < 8; j++) {
            float a0, a1, p0, p1, q0, q1;
            UNPACK2(a0, a1, acc[j]);
            UNPACK2(p0, p1, redsm[0][lane][j]);
            UNPACK2(q0, q1, redsm[1][lane][j]);
            ob[(2 * j) * THW]     = a0 + p0 + q0;
            ob[(2 * j + 1) * THW] = a1 + p1 + q1;
        }
    }
}

extern "C" void kernel_launch(void* const* d_in, const int* in_sizes, int n_in,
                              void* d_out, int out_size)
{
    const float* x    = (const float*)d_in[0];
    const float* temp = (const float*)d_in[1];
    const float* wgt  = (const float*)d_in[2];
    const float* bias = (const float*)d_in[3];
    float* out = (float*)d_out;

    // transpose weights into g_wt, then copy into constant bank
    transpose_w_kernel<<<(NK * NC * NCO + 255) / 256, 256>>>(wgt);
    void* cw_addr = nullptr;
    cudaGetSymbolAddress(&cw_addr, cw);
    void* wt_addr = nullptr;
    cudaGetSymbolAddress(&wt_addr, g_wt);
    cudaMemcpyAsync(cw_addr, wt_addr, NK * NC * NCO * sizeof(float),
                    cudaMemcpyDeviceToDevice, 0);

    const int rows = NB * NT * NH;   // 1024 blocks
    deform_conv3d_hw_kernel<<<rows, TPB>>>(x, temp, bias, out);
}

// round 4
// speedup vs baseline: 1.3778x; 1.3457x over previous
#include <cuda_runtime.h>

// DeformConv3d, dimension='HW': t-offset == 0 -> pure 2D bilinear at integer t.
// R4: x transposed to c4-grouped channels-last [b][t][g][h][w][4] so each
// bilinear corner is one 16B LDG.128 per 4 channels (4x fewer gather instrs
// than R1, far fewer wavefronts than R2's 64B/lane). kt 3-way split for
// occupancy. Weights in smem (LDS.128 broadcast; LDC is floor-8, proven bad).

#define NB  2
#define NC  16
#define NT  8
#define NH  64
#define NW  64
#define NCO 16
#define NK  27
#define HW  (NH * NW)     // 4096
#define THW (NT * HW)     // 32768

#define FMA2(d, a, b) \
    asm("fma.rn.f32x2 %0, %1, %2, %0;" : "+l"(d) : "l"(a), "l"(b))
#define PACK2(d, lo, hi) \
    asm("mov.b64 %0, {%1, %2};" : "=l"(d) : "f"(lo), "f"(hi))
#define UNPACK2(lo, hi, s) \
    asm("mov.b64 {%0, %1}, %2;" : "=f"(lo), "=f"(hi) : "l"(s))

// x in c4-grouped channels-last layout: [b][t][g][hw] of float4 (c = 4g+j)
__device__ __align__(16) float g_x4[NB * NT * 4 * HW * 4];

__global__ void transpose_x_kernel(const float* __restrict__ x)
{
    const int tid = blockIdx.x * blockDim.x + threadIdx.x;  // 0 .. 262143
    const int hw = tid & (HW - 1);
    const int g  = (tid >> 12) & 3;
    const int t  = (tid >> 14) & 7;
    const int b  = tid >> 17;
    float4 v;
    v.x = x[((b * NC + 4 * g + 0) * NT + t) * HW + hw];
    v.y = x[((b * NC + 4 * g + 1) * NT + t) * HW + hw];
    v.z = x[((b * NC + 4 * g + 2) * NT + t) * HW + hw];
    v.w = x[((b * NC + 4 * g + 3) * NT + t) * HW + hw];
    reinterpret_cast<float4*>(g_x4)[tid] = v;
}

// ---------------------------------------------------------------------------
// Block = 192 threads = 3 kt-parts x 64 outputs (one (b,t,h) row).
#define TPB 192

__global__ void __launch_bounds__(TPB, 4)
deform_conv3d_hw_kernel(const float* __restrict__ temp,
                        const float* __restrict__ wgt,
                        const float* __restrict__ bias,
                        float* __restrict__ out)
{
    // weights as [k][c][co]: 16 contiguous co per (k,c) -> LDS.128 broadcast
    __shared__ __align__(16) float wsm[NK * NC * NCO];           // 27648 B
    __shared__ __align__(16) unsigned long long redsm[2][64][8]; // 8192 B

    for (int i = threadIdx.x; i < NK * NC * NCO; i += TPB) {
        int co = i & 15;
        int c  = (i >> 4) & 15;
        int k  = i >> 8;
        wsm[i] = wgt[(co * NC + c) * NK + k];
    }

    const int part = threadIdx.x / 64;   // warp-coherent (warps 0,1 | 2,3 | 4,5)
    const int lane = threadIdx.x & 63;
    const int row  = blockIdx.x;         // b*512 + t*64 + h
    const int w = lane;
    const int h = row & 63;
    const int t = (row >> 6) & 7;
    const int b = row >> 9;
    const int sp = t * HW + h * NW + w;

    unsigned long long acc[8];
    if (part == 0) {
#pragma unroll
        for (int j = 0; j < 8; j++)
            PACK2(acc[j], bias[2 * j], bias[2 * j + 1]);
    } else {
#pragma unroll
        for (int j = 0; j < 8; j++) acc[j] = 0ULL;
    }

    __syncthreads();   // wsm ready

    const int ti = t - 1 + part;
    if (ti >= 0 && ti < NT) {
        // group g's plane: pg = x4base + g*HW (ulonglong2 = one float4 = 4 ch)
        const ulonglong2* __restrict__ x4base =
            reinterpret_cast<const ulonglong2*>(g_x4) + (b * NT + ti) * 4 * HW;
        const float* __restrict__ tb = temp + b * (2 * NK * THW) + sp;
        const int kbase = part * 9;

#pragma unroll
        for (int kh = 0; kh < 3; kh++) {
#pragma unroll
            for (int kw = 0; kw < 3; kw++) {
                const int k = kbase + kh * 3 + kw;

                const float offh = __ldg(tb + (2 * k) * THW);
                const float offw = __ldg(tb + (2 * k + 1) * THW);

                const float ph = (float)(h - 1 + kh) + offh;
                const float pw = (float)(w - 1 + kw) + offw;

                const int h0 = __float2int_rd(ph);
                const int w0 = __float2int_rd(pw);
                const float fh = ph - (float)h0;
                const float fw = pw - (float)w0;
                const int h1 = h0 + 1;
                const int w1 = w0 + 1;

                const bool vh0 = (h0 >= 0) & (h0 < NH);
                const bool vh1 = (h1 >= 0) & (h1 < NH);
                const bool vw0 = (w0 >= 0) & (w0 < NW);
                const bool vw1 = (w1 >= 0) & (w1 < NW);

                const float gh0 = 1.0f - fh, gw0 = 1.0f - fw;
                const float c00 = (vh0 & vw0) ? gh0 * gw0 : 0.0f;
                const float c01 = (vh0 & vw1) ? gh0 * fw  : 0.0f;
                const float c10 = (vh1 & vw0) ? fh  * gw0 : 0.0f;
                const float c11 = (vh1 & vw1) ? fh  * fw  : 0.0f;

                const int h0c = min(max(h0, 0), NH - 1);
                const int h1c = min(max(h1, 0), NH - 1);
                const int w0c = min(max(w0, 0), NW - 1);
                const int w1c = min(max(w1, 0), NW - 1);

                const int i00 = h0c * NW + w0c;
                const int i01 = h0c * NW + w1c;
                const int i10 = h1c * NW + w0c;
                const int i11 = h1c * NW + w1c;

                unsigned long long cc00, cc01, cc10, cc11;
                PACK2(cc00, c00, c00);
                PACK2(cc01, c01, c01);
                PACK2(cc10, c10, c10);
                PACK2(cc11, c11, c11);

#pragma unroll
                for (int g = 0; g < 4; g++) {
                    const ulonglong2* __restrict__ pg = x4base + g * HW;

                    // 4 corners, 4 channels each: bilinear in packed f32x2
                    unsigned long long v01 = 0ULL, v23 = 0ULL;
                    {
                        const ulonglong2 a = __ldg(pg + i00);
                        FMA2(v01, cc00, a.x); FMA2(v23, cc00, a.y);
                    }
                    {
                        const ulonglong2 a = __ldg(pg + i01);
                        FMA2(v01, cc01, a.x); FMA2(v23, cc01, a.y);
                    }
                    {
                        const ulonglong2 a = __ldg(pg + i10);
                        FMA2(v01, cc10, a.x); FMA2(v23, cc10, a.y);
                    }
                    {
                        const ulonglong2 a = __ldg(pg + i11);
                        FMA2(v01, cc11, a.x); FMA2(v23, cc11, a.y);
                    }

                    float u0, u1, u2, u3;
                    UNPACK2(u0, u1, v01);
                    UNPACK2(u2, u3, v23);
                    const float uu[4] = {u0, u1, u2, u3};

                    // GEMM over the 4 channels of this group
#pragma unroll
                    for (int j = 0; j < 4; j++) {
                        unsigned long long vv;
                        asm("mov.b64 %0, {%1, %1};" : "=l"(vv) : "f"(uu[j]));
                        const ulonglong2* wr = (const ulonglong2*)
                            (wsm + (k * NC + 4 * g + j) * NCO);
                        const ulonglong2 q0 = wr[0];
                        const ulonglong2 q1 = wr[1];
                        const ulonglong2 q2 = wr[2];
                        const ulonglong2 q3 = wr[3];
                        FMA2(acc[0], vv, q0.x); FMA2(acc[1], vv, q0.y);
                        FMA2(acc[2], vv, q1.x); FMA2(acc[3], vv, q1.y);
                        FMA2(acc[4], vv, q2.x); FMA2(acc[5], vv, q2.y);
                        FMA2(acc[6], vv, q3.x); FMA2(acc[7], vv, q3.y);
                    }
                }
            }
        }
    }

    if (part > 0) {
#pragma unroll
        for (int j = 0; j < 8; j++)
            redsm[part - 1][lane][j] = acc[j];
    }
    __syncthreads();

    if (part == 0) {
        float* ob = out + b * (NCO * THW) + sp;
#pragma unroll
        for (int j = 0; j < 8; j++) {
            float a0, a1, p0, p1, q0, q1;
            UNPACK2(a0, a1, acc[j]);
            UNPACK2(p0, p1, redsm[0][lane][j]);
            UNPACK2(q0, q1, redsm[1][lane][j]);
            ob[(2 * j) * THW]     = a0 + p0 + q0;
            ob[(2 * j + 1) * THW] = a1 + p1 + q1;
        }
    }
}

extern "C" void kernel_launch(void* const* d_in, const int* in_sizes, int n_in,
                              void* d_out, int out_size)
{
    const float* x    = (const float*)d_in[0];
    const float* temp = (const float*)d_in[1];
    const float* wgt  = (const float*)d_in[2];
    const float* bias = (const float*)d_in[3];
    float* out = (float*)d_out;

    transpose_x_kernel<<<(NB * NT * 4 * HW) / 256, 256>>>(x);

    const int rows = NB * NT * NH;   // 1024 blocks
    deform_conv3d_hw_kernel<<<rows, TPB>>>(temp, wgt, bias, out);
}

// round 5
// speedup vs baseline: 1.8066x; 1.3112x over previous
#include <cuda_runtime.h>

// DeformConv3d, dimension='HW': t-offset == 0 -> pure 2D bilinear at integer t.
// R5: G=4 output points per thread (w = wb+16j) so the per-tap weight LDS
// block (64x LDS.128) is loaded once and reused 4x -> weight L1 traffic /4.
// c4-grouped channels-last gathers (R4) + kt 3-way split kept.

#define NB  2
#define NC  16
#define NT  8
#define NH  64
#define NW  64
#define NCO 16
#define NK  27
#define HW  (NH * NW)     // 4096
#define THW (NT * HW)     // 32768

#define FMA2(d, a, b) \
    asm("fma.rn.f32x2 %0, %1, %2, %0;" : "+l"(d) : "l"(a), "l"(b))
#define PACK2(d, lo, hi) \
    asm("mov.b64 %0, {%1, %2};" : "=l"(d) : "f"(lo), "f"(hi))
#define PACKB(d, s) \
    asm("mov.b64 %0, {%1, %1};" : "=l"(d) : "f"(s))
#define UNPACK2(lo, hi, s) \
    asm("mov.b64 {%0, %1}, %2;" : "=f"(lo), "=f"(hi) : "l"(s))

// x in c4-grouped channels-last layout: [b][t][g][hw] of float4 (c = 4g+j)
__device__ __align__(16) float g_x4[NB * NT * 4 * HW * 4];

__global__ void transpose_x_kernel(const float* __restrict__ x)
{
    const int tid = blockIdx.x * blockDim.x + threadIdx.x;  // 0 .. 262143
    const int hw = tid & (HW - 1);
    const int g  = (tid >> 12) & 3;
    const int t  = (tid >> 14) & 7;
    const int b  = tid >> 17;
    float4 v;
    v.x = x[((b * NC + 4 * g + 0) * NT + t) * HW + hw];
    v.y = x[((b * NC + 4 * g + 1) * NT + t) * HW + hw];
    v.z = x[((b * NC + 4 * g + 2) * NT + t) * HW + hw];
    v.w = x[((b * NC + 4 * g + 3) * NT + t) * HW + hw];
    reinterpret_cast<float4*>(g_x4)[tid] = v;
}

// ---------------------------------------------------------------------------
// Block = 192 threads = 3 kt-parts x 64. Part thread l: hrow = l>>4 (4 rows),
// wb = l&15; thread computes points w = wb + 16j, j = 0..3.
// Block covers (b, t, 4 h-rows) = 256 output points. Grid = 256 blocks.
#define TPB 192

__global__ void __launch_bounds__(TPB, 2)
deform_conv3d_hw_kernel(const float* __restrict__ temp,
                        const float* __restrict__ wgt,
                        const float* __restrict__ bias,
                        float* __restrict__ out)
{
    // weights as [k][c][co]: 16 contiguous co per (k,c) -> LDS.128 broadcast
    __shared__ __align__(16) float wsm[NK * NC * NCO];                // 27648 B
    __shared__ __align__(16) unsigned long long redsm[2][64][2][8];   // 16384 B

    for (int i = threadIdx.x; i < NK * NC * NCO; i += TPB) {
        int co = i & 15;
        int c  = (i >> 4) & 15;
        int k  = i >> 8;
        wsm[i] = wgt[(co * NC + c) * NK + k];
    }

    const int part = threadIdx.x / 64;          // warp-coherent
    const int l    = threadIdx.x & 63;
    const int hrow = l >> 4;
    const int wb   = l & 15;
    const int bid  = blockIdx.x;                // b*128 + t*16 + hgrp
    const int h = ((bid & 15) << 2) + hrow;
    const int t = (bid >> 4) & 7;
    const int b = bid >> 7;

    unsigned long long acc[4][8];
    if (part == 0) {
#pragma unroll
        for (int j = 0; j < 4; j++)
#pragma unroll
            for (int m = 0; m < 8; m++)
                PACK2(acc[j][m], bias[2 * m], bias[2 * m + 1]);
    } else {
#pragma unroll
        for (int j = 0; j < 4; j++)
#pragma unroll
            for (int m = 0; m < 8; m++) acc[j][m] = 0ULL;
    }

    __syncthreads();   // wsm ready

    const int ti = t - 1 + part;
    if (ti >= 0 && ti < NT) {
        const ulonglong2* __restrict__ x4base =
            reinterpret_cast<const ulonglong2*>(g_x4) + (b * NT + ti) * 4 * HW;
        const float* __restrict__ tb =
            temp + b * (2 * NK * THW) + t * HW + h * NW;
        const int kbase = part * 9;

#pragma unroll
        for (int kk = 0; kk < 9; kk++) {
            const int kh = kk / 3;
            const int kw = kk - kh * 3;
            const int k  = kbase + kk;

            float ccf[4][4];
            int   idx[4][4];
#pragma unroll
            for (int j = 0; j < 4; j++) {
                const int w = wb + 16 * j;
                const float offh = __ldg(tb + (2 * k) * THW + w);
                const float offw = __ldg(tb + (2 * k + 1) * THW + w);

                const float ph = (float)(h - 1 + kh) + offh;
                const float pw = (float)(w - 1 + kw) + offw;

                const int h0 = __float2int_rd(ph);
                const int w0 = __float2int_rd(pw);
                const float fh = ph - (float)h0;
                const float fw = pw - (float)w0;
                const int h1 = h0 + 1;
                const int w1 = w0 + 1;

                const bool vh0 = (h0 >= 0) & (h0 < NH);
                const bool vh1 = (h1 >= 0) & (h1 < NH);
                const bool vw0 = (w0 >= 0) & (w0 < NW);
                const bool vw1 = (w1 >= 0) & (w1 < NW);

                const float gh0 = 1.0f - fh, gw0 = 1.0f - fw;
                ccf[j][0] = (vh0 & vw0) ? gh0 * gw0 : 0.0f;
                ccf[j][1] = (vh0 & vw1) ? gh0 * fw  : 0.0f;
                ccf[j][2] = (vh1 & vw0) ? fh  * gw0 : 0.0f;
                ccf[j][3] = (vh1 & vw1) ? fh  * fw  : 0.0f;

                const int h0c = min(max(h0, 0), NH - 1);
                const int h1c = min(max(h1, 0), NH - 1);
                const int w0c = min(max(w0, 0), NW - 1);
                const int w1c = min(max(w1, 0), NW - 1);
                idx[j][0] = h0c * NW + w0c;
                idx[j][1] = h0c * NW + w1c;
                idx[j][2] = h1c * NW + w0c;
                idx[j][3] = h1c * NW + w1c;
            }

#pragma unroll
            for (int g = 0; g < 4; g++) {
                const ulonglong2* __restrict__ pg = x4base + g * HW;

                // bilinear values for 4 points: u[j] packs channels
                // {4g,4g+1} (lo) and {4g+2,4g+3} (hi)
                unsigned long long u[4][2];
#pragma unroll
                for (int j = 0; j < 4; j++) {
                    u[j][0] = 0ULL; u[j][1] = 0ULL;
#pragma unroll
                    for (int q = 0; q < 4; q++) {
                        unsigned long long cc;
                        PACKB(cc, ccf[j][q]);
                        const ulonglong2 a = __ldg(pg + idx[j][q]);
                        FMA2(u[j][0], cc, a.x);
                        FMA2(u[j][1], cc, a.y);
                    }
                }

                // GEMM: weights for channels 4g..4g+3, loaded once, used 4x
                const ulonglong2* __restrict__ wr =
                    (const ulonglong2*)(wsm + (k * NC + 4 * g) * NCO);
#pragma unroll
                for (int cp = 0; cp < 2; cp++) {
                    // channel 4g+2cp (even of pair)
                    const ulonglong2 q0 = wr[cp * 8 + 0];
                    const ulonglong2 q1 = wr[cp * 8 + 1];
                    const ulonglong2 q2 = wr[cp * 8 + 2];
                    const ulonglong2 q3 = wr[cp * 8 + 3];
                    // channel 4g+2cp+1 (odd of pair)
                    const ulonglong2 r0 = wr[cp * 8 + 4];
                    const ulonglong2 r1 = wr[cp * 8 + 5];
                    const ulonglong2 r2 = wr[cp * 8 + 6];
                    const ulonglong2 r3 = wr[cp * 8 + 7];
#pragma unroll
                    for (int j = 0; j < 4; j++) {
                        float v0, v1;
                        UNPACK2(v0, v1, u[j][cp]);
                        unsigned long long vv0, vv1;
                        PACKB(vv0, v0);
                        PACKB(vv1, v1);
                        FMA2(acc[j][0], vv0, q0.x); FMA2(acc[j][1], vv0, q0.y);
                        FMA2(acc[j][2], vv0, q1.x); FMA2(acc[j][3], vv0, q1.y);
                        FMA2(acc[j][4], vv0, q2.x); FMA2(acc[j][5], vv0, q2.y);
                        FMA2(acc[j][6], vv0, q3.x); FMA2(acc[j][7], vv0, q3.y);
                        FMA2(acc[j][0], vv1, r0.x); FMA2(acc[j][1], vv1, r0.y);
                        FMA2(acc[j][2], vv1, r1.x); FMA2(acc[j][3], vv1, r1.y);
                        FMA2(acc[j][4], vv1, r2.x); FMA2(acc[j][5], vv1, r2.y);
                        FMA2(acc[j][6], vv1, r3.x); FMA2(acc[j][7], vv1, r3.y);
                    }
                }
            }
        }
    }

    // reduce parts 1,2 into part 0 through smem, two j-waves to bound smem
#pragma unroll
    for (int wave = 0; wave < 2; wave++) {
        if (part > 0) {
#pragma unroll
            for (int jj = 0; jj < 2; jj++)
#pragma unroll
                for (int m = 0; m < 8; m++)
                    redsm[part - 1][l][jj][m] = acc[2 * wave + jj][m];
        }
        __syncthreads();
        if (part == 0) {
#pragma unroll
            for (int jj = 0; jj < 2; jj++) {
                const int j = 2 * wave + jj;
                float* ob = out + b * (NCO * THW) + t * HW + h * NW
                            + wb + 16 * j;
#pragma unroll
                for (int m = 0; m < 8; m++) {
                    float a0, a1, p0, p1, q0, q1;
                    UNPACK2(a0, a1, acc[j][m]);
                    UNPACK2(p0, p1, redsm[0][l][jj][m]);
                    UNPACK2(q0, q1, redsm[1][l][jj][m]);
                    ob[(2 * m) * THW]     = a0 + p0 + q0;
                    ob[(2 * m + 1) * THW] = a1 + p1 + q1;
                }
            }
        }
        __syncthreads();
    }
}

extern "C" void kernel_launch(void* const* d_in, const int* in_sizes, int n_in,
                              void* d_out, int out_size)
{
    const float* x    = (const float*)d_in[0];
    const float* temp = (const float*)d_in[1];
    const float* wgt  = (const float*)d_in[2];
    const float* bias = (const float*)d_in[3];
    float* out = (float*)d_out;

    transpose_x_kernel<<<(NB * NT * 4 * HW) / 256, 256>>>(x);

    deform_conv3d_hw_kernel<<<256, TPB>>>(temp, wgt, bias, out);
}